// round 6
// baseline (speedup 1.0000x reference)
#include <cuda_runtime.h>
#include <cuda_bf16.h>

// Problem constants (from reference setup_inputs):
//   bs=4, c=3, dsrc=1, h=w=128, d=8, K=10 -> K1=11, out_channels=66
//   out shape (bs, 66, d, h, w) float32
#define BS   4
#define CCH  3
#define HH   128
#define WW   128
#define DD   8
#define KK   10
#define K1   (KK + 1)
#define HW   (HH * WW)          // 16384
#define NKP  (BS * DD * KK)     // 320
#define NREST (BS * DD * K1)    // 352

// scratch: reciprocal of heatmap sums, one per (b, d, k)
__device__ float g_inv_sum[NKP];

// ---------------------------------------------------------------------------
// Kernel 1: per-(b,d,k) sum of exp(-0.5*|grid - mu|^2 / 0.01) over the grid.
// One block per keypoint, 256 threads, warp-shuffle + smem reduce.
// ---------------------------------------------------------------------------
__global__ void heat_sum_kernel(const float* __restrict__ kp_drv) {
    const int idx = blockIdx.x;                 // 0..319  == (b*8+dd)*10 + k
    const float mx = kp_drv[2 * idx + 0];
    const float my = kp_drv[2 * idx + 1];

    float s = 0.0f;
    for (int i = threadIdx.x; i < HW; i += blockDim.x) {
        const float gx = (float)(i & (WW - 1)) * (2.0f / (WW - 1)) - 1.0f;
        const float gy = (float)(i >> 7)       * (2.0f / (HH - 1)) - 1.0f;
        const float dx = gx - mx;
        const float dy = gy - my;
        s += __expf(-50.0f * (dx * dx + dy * dy));   // -0.5/0.01 = -50
    }

    #pragma unroll
    for (int off = 16; off > 0; off >>= 1)
        s += __shfl_xor_sync(0xFFFFFFFFu, s, off);

    __shared__ float red[8];
    const int wid = threadIdx.x >> 5;
    const int lid = threadIdx.x & 31;
    if (lid == 0) red[wid] = s;
    __syncthreads();
    if (wid == 0) {
        float v = (lid < (blockDim.x >> 5)) ? red[lid] : 0.0f;
        #pragma unroll
        for (int off = 4; off > 0; off >>= 1)
            v += __shfl_xor_sync(0xFFFFFFFFu, v, off);
        if (lid == 0) g_inv_sum[idx] = 1.0f / v;
    }
}

// ---------------------------------------------------------------------------
// Kernel 2: one thread = 4 consecutive x pixels of one (b, dd, k1, y) row.
// Writes 6 channels as float4 each:
//   ch k1*6+0 : normalized heat (0 for k1==0)
//   ch k1*6+1 : diffx  (constant per (b,dd,k1))
//   ch k1*6+2 : diffy
//   ch k1*6+3..5 : source image bilinearly sampled at constant shift.
// Key facts exploited: shift is constant per (b,dd,k1), so the bilinear
// fractional weights are identical across x; corner columns for 4 pixels are
// the 5 consecutive columns ix0..ix0+4.
// Output layout: out[(((b*66 + ch)*8 + dd)*128 + y)*128 + x]
// ---------------------------------------------------------------------------
__global__ void movement_embed_kernel(const float* __restrict__ src,
                                      const float* __restrict__ kp_drv,
                                      const float* __restrict__ kp_src,
                                      float* __restrict__ out) {
    const int tid  = blockIdx.x * blockDim.x + threadIdx.x;
    const int xq   = tid & 31;                 // x quad index: x = xq*4 .. xq*4+3
    const int y    = (tid >> 5) & (HH - 1);
    const int rest = tid >> 12;                // 0..351
    if (rest >= NREST) return;
    const int k1 = rest % K1;
    const int bd = rest / K1;                  // b*8 + dd
    const int b  = bd >> 3;

    const int xb = xq << 2;                    // base x of the quad

    float diffx = 0.0f, diffy = 0.0f, inv_s = 0.0f;
    float mx = 0.0f, my = 0.0f;
    if (k1 > 0) {
        const int kidx = bd * KK + (k1 - 1);
        mx = kp_drv[2 * kidx + 0];
        my = kp_drv[2 * kidx + 1];
        diffx = kp_src[2 * kidx + 0] - mx;
        diffy = kp_src[2 * kidx + 1] - my;
        inv_s = g_inv_sum[kidx];
    }

    // ---- heat: separable gaussian, row factor shared by the 4 pixels ----
    float4 heat4 = make_float4(0.f, 0.f, 0.f, 0.f);
    if (k1 > 0) {
        const float gy = (float)y * (2.0f / (HH - 1)) - 1.0f;
        const float dy = gy - my;
        const float ey = __expf(-50.0f * dy * dy) * inv_s;
        float h[4];
        #pragma unroll
        for (int i = 0; i < 4; i++) {
            const float gx = (float)(xb + i) * (2.0f / (WW - 1)) - 1.0f;
            const float dx = gx - mx;
            h[i] = __expf(-50.0f * dx * dx) * ey;
        }
        heat4 = make_float4(h[0], h[1], h[2], h[3]);
    }

    // ---- bilinear sample at constant pixel shift, zero padding ----
    const float sx = diffx * (0.5f * (WW - 1));   // * 63.5
    const float sy = diffy * (0.5f * (HH - 1));
    const float py = (float)y + sy;
    const float fy = floorf(py);
    const int   iy0 = (int)fy, iy1 = iy0 + 1;
    const float wy1 = py - fy, wy0 = 1.0f - wy1;
    const float vy0 = ((unsigned)iy0 < (unsigned)HH) ? 1.0f : 0.0f;
    const float vy1 = ((unsigned)iy1 < (unsigned)HH) ? 1.0f : 0.0f;
    const float wy0v = wy0 * vy0, wy1v = wy1 * vy1;
    const int cy0 = min(max(iy0, 0), HH - 1);
    const int cy1 = min(max(iy1, 0), HH - 1);

    const float px0 = (float)xb + sx;
    const float fx  = floorf(px0);
    const int   ix0 = (int)fx;
    const float wx1 = px0 - fx, wx0 = 1.0f - wx1;

    int   ccol[5];
    float cmask[5];
    #pragma unroll
    for (int j = 0; j < 5; j++) {
        const int xj = ix0 + j;
        cmask[j] = ((unsigned)xj < (unsigned)WW) ? 1.0f : 0.0f;
        ccol[j]  = min(max(xj, 0), WW - 1);
    }

    // ---- output addressing ----
    const int chs = DD * HW;                               // per-channel stride (fits int)
    const int base = ((b * (K1 * 6) + k1 * 6) * DD + (bd & (DD - 1))) * HW
                     + (y << 7) + xb;
    float* o = out + base;

    *(float4*)(o)            = heat4;
    *(float4*)(o + chs)      = make_float4(diffx, diffx, diffx, diffx);
    *(float4*)(o + 2 * chs)  = make_float4(diffy, diffy, diffy, diffy);

    const float* im = src + b * (CCH * HW);
    #pragma unroll
    for (int cc = 0; cc < CCH; cc++) {
        const float* r0 = im + cc * HW + (cy0 << 7);
        const float* r1 = im + cc * HW + (cy1 << 7);
        float a0[5], a1[5];
        #pragma unroll
        for (int j = 0; j < 5; j++) {
            a0[j] = r0[ccol[j]] * cmask[j];
            a1[j] = r1[ccol[j]] * cmask[j];
        }
        float v[4];
        #pragma unroll
        for (int i = 0; i < 4; i++) {
            v[i] = wy0v * (wx0 * a0[i] + wx1 * a0[i + 1])
                 + wy1v * (wx0 * a1[i] + wx1 * a1[i + 1]);
        }
        *(float4*)(o + (3 + cc) * chs) = make_float4(v[0], v[1], v[2], v[3]);
    }
}

// ---------------------------------------------------------------------------
extern "C" void kernel_launch(void* const* d_in, const int* in_sizes, int n_in,
                              void* d_out, int out_size) {
    const float* src    = (const float*)d_in[0];  // (4,3,1,128,128)
    const float* kp_drv = (const float*)d_in[1];  // (4,8,10,2)
    const float* kp_src = (const float*)d_in[2];  // (4,8,10,2)
    float* out = (float*)d_out;                   // (4,66,8,128,128)

    heat_sum_kernel<<<NKP, 256>>>(kp_drv);

    const int total   = NREST * HH * (WW / 4);    // 1,441,792 threads
    const int threads = 256;
    const int blocks  = (total + threads - 1) / threads;  // 5632
    movement_embed_kernel<<<blocks, threads>>>(src, kp_drv, kp_src, out);
}

// round 7
// speedup vs baseline: 1.1221x; 1.1221x over previous
#include <cuda_runtime.h>
#include <cuda_bf16.h>

// Problem constants:
//   bs=4, c=3, dsrc=1, h=w=128, d=8, K=10 -> K1=11, out_channels=66
//   out shape (bs, 66, d, h, w) float32
#define BS   4
#define CCH  3
#define HH   128
#define WW   128
#define DD   8
#define KK   10
#define K1   (KK + 1)
#define HW   (HH * WW)          // 16384
#define NKP  (BS * DD * KK)     // 320
#define NREST (BS * DD * K1)    // 352

// scratch: separable normalized gaussian tables, per (b,d,k)
__device__ float g_ex[NKP * WW];   // exp(-50*(gx-mx)^2) / Sx
__device__ float g_ey[NKP * HH];   // exp(-50*(gy-my)^2) / Sy

// ---------------------------------------------------------------------------
// Kernel 1: per-keypoint separable gaussian tables + normalization.
// One block (128 threads) per keypoint; thread t handles x=t and y=t.
// ---------------------------------------------------------------------------
__global__ void heat_table_kernel(const float* __restrict__ kp_drv) {
    const int idx = blockIdx.x;                 // 0..319
    const int t   = threadIdx.x;                // 0..127
    const float mx = kp_drv[2 * idx + 0];
    const float my = kp_drv[2 * idx + 1];

    const float g = (float)t * (2.0f / (WW - 1)) - 1.0f;
    const float dx = g - mx;
    const float dy = g - my;
    const float ex = __expf(-50.0f * dx * dx);
    const float ey = __expf(-50.0f * dy * dy);

    // reduce Sx, Sy over 128 threads (4 warps)
    float sx = ex, sy = ey;
    #pragma unroll
    for (int off = 16; off > 0; off >>= 1) {
        sx += __shfl_xor_sync(0xFFFFFFFFu, sx, off);
        sy += __shfl_xor_sync(0xFFFFFFFFu, sy, off);
    }
    __shared__ float rx[4], ry[4];
    const int wid = t >> 5, lid = t & 31;
    if (lid == 0) { rx[wid] = sx; ry[wid] = sy; }
    __syncthreads();
    const float Sx = rx[0] + rx[1] + rx[2] + rx[3];
    const float Sy = ry[0] + ry[1] + ry[2] + ry[3];

    g_ex[idx * WW + t] = ex / Sx;
    g_ey[idx * HH + t] = ey / Sy;
}

// uniform-r 5-element window select out of two float4s (r uniform per block)
__device__ __forceinline__ void sel5(const float4& qa, const float4& qb, int r,
                                     float o[5]) {
    switch (r) {
        case 0:  o[0]=qa.x; o[1]=qa.y; o[2]=qa.z; o[3]=qa.w; o[4]=qb.x; break;
        case 1:  o[0]=qa.y; o[1]=qa.z; o[2]=qa.w; o[3]=qb.x; o[4]=qb.y; break;
        case 2:  o[0]=qa.z; o[1]=qa.w; o[2]=qb.x; o[3]=qb.y; o[4]=qb.z; break;
        default: o[0]=qa.w; o[1]=qb.x; o[2]=qb.y; o[3]=qb.z; o[4]=qb.w; break;
    }
}

// ---------------------------------------------------------------------------
// Kernel 2: one thread = 4 consecutive x pixels of one (b, dd, k1, y) row.
// 6 float4 stores per thread:
//   heat (table product), diffx, diffy, 3x bilinear-shifted source channels.
// Gather uses two aligned float4 loads per (row,channel): the per-block
// misalignment r = floor(sx) & 3 is uniform, so a uniform switch selects the
// 5-column window. Clamped-load elements always carry out-of-range column
// labels and are zero-masked.
// ---------------------------------------------------------------------------
__global__ void movement_embed_kernel(const float* __restrict__ src,
                                      const float* __restrict__ kp_drv,
                                      const float* __restrict__ kp_src,
                                      float* __restrict__ out) {
    const int tid  = blockIdx.x * blockDim.x + threadIdx.x;
    const int xq   = tid & 31;                 // x quad: x = xq*4 .. xq*4+3
    const int y    = (tid >> 5) & (HH - 1);
    const int rest = tid >> 12;                // 0..351 (uniform per block)
    const int k1 = rest % K1;
    const int bd = rest / K1;                  // b*8 + dd
    const int b  = bd >> 3;
    const int xb = xq << 2;

    float diffx = 0.0f, diffy = 0.0f;
    float4 heat4 = make_float4(0.f, 0.f, 0.f, 0.f);
    if (k1 > 0) {
        const int kidx = bd * KK + (k1 - 1);
        diffx = kp_src[2 * kidx + 0] - kp_drv[2 * kidx + 0];
        diffy = kp_src[2 * kidx + 1] - kp_drv[2 * kidx + 1];
        const float ey  = g_ey[kidx * HH + y];               // warp-uniform
        const float4 ex = *(const float4*)&g_ex[kidx * WW + xb];
        heat4 = make_float4(ex.x * ey, ex.y * ey, ex.z * ey, ex.w * ey);
    }

    // ---- constant per-(b,dd,k1) pixel shift ----
    const float sx = diffx * (0.5f * (WW - 1));   // * 63.5
    const float sy = diffy * (0.5f * (HH - 1));

    // y interpolation (weights fold in y-validity; rows address-clamped)
    const float py  = (float)y + sy;
    const float fy  = floorf(py);
    const int   iy0 = (int)fy, iy1 = iy0 + 1;
    const float wy1 = py - fy, wy0 = 1.0f - wy1;
    const float wy0v = wy0 * (((unsigned)iy0 < (unsigned)HH) ? 1.0f : 0.0f);
    const float wy1v = wy1 * (((unsigned)iy1 < (unsigned)HH) ? 1.0f : 0.0f);
    const int cy0 = min(max(iy0, 0), HH - 1);
    const int cy1 = min(max(iy1, 0), HH - 1);

    // x: aligned two-float4 window
    const int   isx = (int)floorf(sx);
    const float wx1 = sx - floorf(sx), wx0 = 1.0f - wx1;
    const int   r   = isx & 3;                     // uniform per block
    const int   ix0 = xb + isx;                    // first needed column
    const int   B   = xb + (isx & ~3);             // aligned window base
    const int   o0  = min(max(B, 0), WW - 4);      // clamped aligned addrs
    const int   o1  = min(max(B + 4, 0), WW - 4);

    float amask[5];
    #pragma unroll
    for (int j = 0; j < 5; j++)
        amask[j] = ((unsigned)(ix0 + j) < (unsigned)WW) ? 1.0f : 0.0f;

    // ---- output ----
    const int chs  = DD * HW;
    const int base = ((b * (K1 * 6) + k1 * 6) * DD + (bd & (DD - 1))) * HW
                     + (y << 7) + xb;
    float* o = out + base;

    *(float4*)(o)           = heat4;
    *(float4*)(o + chs)     = make_float4(diffx, diffx, diffx, diffx);
    *(float4*)(o + 2 * chs) = make_float4(diffy, diffy, diffy, diffy);

    const float* im = src + b * (CCH * HW);
    #pragma unroll
    for (int cc = 0; cc < CCH; cc++) {
        const float* r0p = im + cc * HW + (cy0 << 7);
        const float* r1p = im + cc * HW + (cy1 << 7);
        const float4 q00 = *(const float4*)(r0p + o0);
        const float4 q01 = *(const float4*)(r0p + o1);
        const float4 q10 = *(const float4*)(r1p + o0);
        const float4 q11 = *(const float4*)(r1p + o1);

        float a0[5], a1[5];
        sel5(q00, q01, r, a0);
        sel5(q10, q11, r, a1);
        #pragma unroll
        for (int j = 0; j < 5; j++) { a0[j] *= amask[j]; a1[j] *= amask[j]; }

        float v[4];
        #pragma unroll
        for (int i = 0; i < 4; i++)
            v[i] = wy0v * (wx0 * a0[i] + wx1 * a0[i + 1])
                 + wy1v * (wx0 * a1[i] + wx1 * a1[i + 1]);
        *(float4*)(o + (3 + cc) * chs) = make_float4(v[0], v[1], v[2], v[3]);
    }
}

// ---------------------------------------------------------------------------
extern "C" void kernel_launch(void* const* d_in, const int* in_sizes, int n_in,
                              void* d_out, int out_size) {
    const float* src    = (const float*)d_in[0];  // (4,3,1,128,128)
    const float* kp_drv = (const float*)d_in[1];  // (4,8,10,2)
    const float* kp_src = (const float*)d_in[2];  // (4,8,10,2)
    float* out = (float*)d_out;                   // (4,66,8,128,128)

    heat_table_kernel<<<NKP, 128>>>(kp_drv);

    const int total   = NREST * HH * (WW / 4);    // 1,441,792 threads (exact)
    const int threads = 256;
    const int blocks  = total / threads;          // 5632
    movement_embed_kernel<<<blocks, threads>>>(src, kp_drv, kp_src, out);
}